// round 16
// baseline (speedup 1.0000x reference)
#include <cuda_runtime.h>
#include <cuda_bf16.h>
#include <cuda_fp16.h>
#include <cstdint>

#define B_ 4
#define H_ 8
#define N_ 2048
#define D_ 64
#define KTOP 16
#define FSCALE (1.0f/64.0f)
#define MARGIN 0.08f
#define NCAND 96

#define NIT 8               // 512 / BK, BK=64 (one head per iter)
#define STAGE_BYTES 32768   // A tile 16KB + B tile 16KB
#define SMEM_TOTAL (2 * STAGE_BYTES)   // 64KB -> 2 CTAs/SM

// ---- global scratch (allocation-free rule: __device__ globals) ----
__device__ unsigned short g_zb[(size_t)B_ * N_ * N_];   // z_approx bf16 bits
__device__ __half g_gb[(size_t)B_ * N_ * N_];           // gumbel(u) fp16
__device__ __nv_bfloat16 g_qs[(size_t)B_ * H_ * N_ * D_];
__device__ __nv_bfloat16 g_ks[(size_t)B_ * H_ * N_ * D_];

// ---------------------------------------------------------------------------
// helpers
// ---------------------------------------------------------------------------
__device__ __forceinline__ uint32_t smem_to_u32(const void* p) {
    uint32_t a;
    asm("{ .reg .u64 t; cvta.to.shared.u64 t, %1; cvt.u32.u64 %0, t; }" : "=r"(a) : "l"(p));
    return a;
}
__device__ __forceinline__ uint32_t tile_off(int row, int chunk) {
    return (uint32_t)(row * 128 + ((chunk ^ (row & 7)) << 4));
}
__device__ __forceinline__ void cp16(uint32_t dst, const void* src) {
    asm volatile("cp.async.cg.shared.global [%0], [%1], 16;" :: "r"(dst), "l"(src) : "memory");
}
__device__ __forceinline__ void cp_commit() {
    asm volatile("cp.async.commit_group;" ::: "memory");
}
template<int Ng> __device__ __forceinline__ void cp_wait() {
    asm volatile("cp.async.wait_group %0;" :: "n"(Ng) : "memory");
}
__device__ __forceinline__ void ldsm4(uint32_t* r, uint32_t addr) {
    asm volatile("ldmatrix.sync.aligned.m8n8.x4.shared.b16 {%0,%1,%2,%3}, [%4];"
                 : "=r"(r[0]), "=r"(r[1]), "=r"(r[2]), "=r"(r[3]) : "r"(addr));
}
__device__ __forceinline__ void mma_bf16(float* c, const uint32_t* a,
                                         uint32_t b0, uint32_t b1) {
    asm volatile(
        "mma.sync.aligned.m16n8k16.row.col.f32.bf16.bf16.f32 "
        "{%0,%1,%2,%3}, {%4,%5,%6,%7}, {%8,%9}, {%0,%1,%2,%3};"
        : "+f"(c[0]), "+f"(c[1]), "+f"(c[2]), "+f"(c[3])
        : "r"(a[0]), "r"(a[1]), "r"(a[2]), "r"(a[3]), "r"(b0), "r"(b1));
}
// accurate gumbel (exact refine path only)
__device__ __forceinline__ float gumbel_of(float u) {
    return -logf(-logf(u + 1e-9f) + 1e-9f);
}
// fast polynomial ln: range-reduce m in [2/3, 4/3), degree-7 Taylor.
__device__ __forceinline__ float fast_ln(float x) {
    const int i = __float_as_int(x);
    const int e = (i - 0x3f2aaaab) >> 23;            // arithmetic shift
    const float m = __int_as_float(i - (e << 23));   // in [2/3, 4/3)
    const float t = m - 1.0f;
    float p = -0.142857143f;
    p = fmaf(p, t, 0.166666667f);
    p = fmaf(p, t, -0.2f);
    p = fmaf(p, t, 0.25f);
    p = fmaf(p, t, -0.333333333f);
    p = fmaf(p, t, 0.5f);
    p = fmaf(p, t, -1.0f);
    return fmaf((float)e, 0.693147181f, -t * p);
}
__device__ __forceinline__ float gumbel_fast(float u) {
    const float v = -fast_ln(u + 1e-9f);
    return -fast_ln(v + 1e-9f);
}
__device__ __forceinline__ uint32_t pack_bf2(float a, float b) {
    return (uint32_t)__bfloat16_as_ushort(__float2bfloat16_rn(a))
         | ((uint32_t)__bfloat16_as_ushort(__float2bfloat16_rn(b)) << 16);
}
__device__ __forceinline__ float bf_bits2f(unsigned short v) {
    return __bfloat162float(__ushort_as_bfloat16(v));
}

// ---------------------------------------------------------------------------
// Kernel 0: grid (8192, 2).
//  y==0: u -> gumbel_fast -> fp16 plane (8192 blocks cover 16.7M elements)
//  y==1: blocks 0..2047 cast q -> bf16; 2048..4095 cast k; rest idle.
// ---------------------------------------------------------------------------
__global__ __launch_bounds__(256) void convert_kernel(
    const float* __restrict__ q, const float* __restrict__ k,
    const float* __restrict__ u)
{
    if (blockIdx.y == 0) {
        const size_t e = ((size_t)blockIdx.x * 256 + threadIdx.x) * 8;
        float4 a = *(const float4*)(u + e);
        float4 b = *(const float4*)(u + e + 4);
        __half2 h0 = __floats2half2_rn(gumbel_fast(a.x), gumbel_fast(a.y));
        __half2 h1 = __floats2half2_rn(gumbel_fast(a.z), gumbel_fast(a.w));
        __half2 h2 = __floats2half2_rn(gumbel_fast(b.x), gumbel_fast(b.y));
        __half2 h3 = __floats2half2_rn(gumbel_fast(b.z), gumbel_fast(b.w));
        uint4 o;
        o.x = *(uint32_t*)&h0; o.y = *(uint32_t*)&h1;
        o.z = *(uint32_t*)&h2; o.w = *(uint32_t*)&h3;
        *(uint4*)(g_gb + e) = o;
    } else {
        if (blockIdx.x >= 4096) return;
        const int isk = blockIdx.x >> 11;
        const size_t e = (((size_t)(blockIdx.x & 2047)) * 256 + threadIdx.x) * 8;
        const float* src = isk ? k : q;
        __nv_bfloat16* dst = isk ? g_ks : g_qs;
        float4 a = *(const float4*)(src + e);
        float4 b = *(const float4*)(src + e + 4);
        uint4 o;
        o.x = pack_bf2(a.x, a.y);
        o.y = pack_bf2(a.z, a.w);
        o.z = pack_bf2(b.x, b.y);
        o.w = pack_bf2(b.z, b.w);
        *(uint4*)(dst + e) = o;
    }
}

// ---------------------------------------------------------------------------
// Kernel 1: 1-term bf16 mma.sync GEMM + precomputed fp16 gumbel -> z bf16.
// CTA tile 128x128, BK=64, 512 threads = 16 warps (4m x 4n), warp tile 32x32.
// 2 CTAs/SM, cp.async 2-stage pipeline.
// ---------------------------------------------------------------------------
__global__ __launch_bounds__(512, 2) void gemm_approx_kernel()
{
    extern __shared__ char smem[];
    const uint32_t sbase = smem_to_u32(smem);

    const int tid = threadIdx.x;
    const int lid = tid & 31;
    const int wid = tid >> 5;
    const int wm  = wid >> 2;
    const int wn  = wid & 3;

    const int b  = blockIdx.z;
    const int m0 = blockIdx.x * 128;
    const int n0 = blockIdx.y * 128;

    const int lrow  = (tid & 255) >> 1;
    const int lhalf = tid & 1;
    const __nv_bfloat16* lsrc0 = (tid < 256)
        ? g_qs + ((size_t)(b * H_) * N_ + (n0 + lrow)) * D_ + lhalf * 32
        : g_ks + ((size_t)(b * H_) * N_ + (m0 + lrow)) * D_ + lhalf * 32;
    const uint32_t my_tile = (tid < 256) ? 0u : 16384u;
    const size_t plane = (size_t)N_ * D_;

    float acc[2][4][4];
#pragma unroll
    for (int i = 0; i < 2; i++)
#pragma unroll
        for (int j = 0; j < 4; j++)
#pragma unroll
            for (int t = 0; t < 4; t++) acc[i][j][t] = 0.0f;

    const int ar = lid & 15;
    const int ac = lid >> 4;
    const int br = (lid & 7) + ((lid >> 4) << 3);
    const int bc = (lid >> 3) & 1;

    {
        const uint32_t dbase = sbase + my_tile;
#pragma unroll
        for (int c = 0; c < 4; c++)
            cp16(dbase + tile_off(lrow, lhalf * 4 + c), (const char*)lsrc0 + c * 16);
        cp_commit();
    }

#pragma unroll 1
    for (int it = 0; it < NIT; it++) {
        const int stg = it & 1;
        cp_wait<0>();
        __syncthreads();

        if (it + 1 < NIT) {
            const __nv_bfloat16* src = lsrc0 + (size_t)(it + 1) * plane;
            const uint32_t dbase = sbase + (uint32_t)((1 - stg) * STAGE_BYTES) + my_tile;
#pragma unroll
            for (int c = 0; c < 4; c++)
                cp16(dbase + tile_off(lrow, lhalf * 4 + c), (const char*)src + c * 16);
            cp_commit();
        }

        const uint32_t abase   = sbase + (uint32_t)(stg * STAGE_BYTES);
        const uint32_t bbase_s = abase + 16384u;

#pragma unroll
        for (int s = 0; s < 4; s++) {
            uint32_t ah[2][4], bb[2][4];
            ldsm4(ah[0], abase + tile_off(wm * 32 + ar, s * 2 + ac));
            ldsm4(ah[1], abase + tile_off(wm * 32 + 16 + ar, s * 2 + ac));
            ldsm4(bb[0], bbase_s + tile_off(wn * 32 + br, s * 2 + bc));
            ldsm4(bb[1], bbase_s + tile_off(wn * 32 + 16 + br, s * 2 + bc));
#pragma unroll
            for (int g = 0; g < 2; g++)
#pragma unroll
                for (int mf = 0; mf < 2; mf++) {
                    mma_bf16(acc[mf][g * 2 + 0], ah[mf], bb[g][0], bb[g][1]);
                    mma_bf16(acc[mf][g * 2 + 1], ah[mf], bb[g][2], bb[g][3]);
                }
        }
    }

    // Epilogue: z = acc*FSCALE + gumbel_fp16 -> bf16 in g_zb
    const int r4 = lid >> 2;
    const int c2 = (lid & 3) * 2;
#pragma unroll
    for (int mf = 0; mf < 2; mf++) {
#pragma unroll
        for (int rr = 0; rr < 2; rr++) {
            const int row = n0 + wm * 32 + mf * 16 + r4 + rr * 8;
            const size_t rbase = ((size_t)b * N_ + row) * N_ + m0 + wn * 32;
            const __half* grow = g_gb + rbase;
            unsigned short* zrow = g_zb + rbase;
#pragma unroll
            for (int j = 0; j < 4; j++) {
                const int co = (j >> 1) * 16 + (j & 1) * 8 + c2;
                float2 gv = __half22float2(*(const __half2*)(grow + co));
                const float zx = acc[mf][j][rr * 2 + 0] * FSCALE + gv.x;
                const float zy = acc[mf][j][rr * 2 + 1] * FSCALE + gv.y;
                *(uint32_t*)(zrow + co) = pack_bf2(zx, zy);
            }
        }
    }
}

// ---------------------------------------------------------------------------
// Kernel 2: 16-bit radix select on z_approx (2 passes) -> candidates within
// MARGIN -> exact fp32 recompute (original q,k) -> exact 16th-largest -> mask.
// (R14 version: one row per 256-thread block)
// ---------------------------------------------------------------------------
__device__ __forceinline__ uint32_t bf2ord(unsigned short v) {
    return (v & 0x8000u) ? ((~(uint32_t)v) & 0xFFFFu) : ((uint32_t)v | 0x8000u);
}
__device__ __forceinline__ float ord2bf(uint32_t o) {
    unsigned short v = (o & 0x8000u) ? (unsigned short)(o & 0x7FFFu)
                                     : (unsigned short)((~o) & 0xFFFFu);
    return bf_bits2f(v);
}

__global__ __launch_bounds__(256) void topk_refine_kernel(
    const float* __restrict__ q, const float* __restrict__ k,
    const float* __restrict__ u, float* __restrict__ out)
{
    const int row = blockIdx.x;            // b*2048 + n
    const int b = row >> 11;
    const int n = row & 2047;
    const int tid = threadIdx.x;
    const int lid = tid & 31, wid = tid >> 5;

    __shared__ int      hist[256];
    __shared__ uint32_t s_prefix;
    __shared__ int      s_k;
    __shared__ float    qs[512];
    __shared__ int      scols[NCAND];
    __shared__ float    cand_z[NCAND];
    __shared__ int      scount;
    __shared__ float    s_thresh;

    const unsigned short* zr = g_zb + (size_t)row * N_;
    uint4 rz = ((const uint4*)zr)[tid];
    unsigned short vb[8] = {
        (unsigned short)(rz.x & 0xFFFF), (unsigned short)(rz.x >> 16),
        (unsigned short)(rz.y & 0xFFFF), (unsigned short)(rz.y >> 16),
        (unsigned short)(rz.z & 0xFFFF), (unsigned short)(rz.z >> 16),
        (unsigned short)(rz.w & 0xFFFF), (unsigned short)(rz.w >> 16)};
    uint32_t key[8];
    float vals[8];
#pragma unroll
    for (int j = 0; j < 8; j++) { key[j] = bf2ord(vb[j]); vals[j] = bf_bits2f(vb[j]); }

    {
        int c = tid;
        qs[c] = q[(((size_t)(b * H_ + (c >> 6)) * N_ + n) << 6) + (c & 63)];
        c = tid + 256;
        qs[c] = q[(((size_t)(b * H_ + (c >> 6)) * N_ + n) << 6) + (c & 63)];
    }
    if (tid == 0) { s_prefix = 0u; s_k = KTOP; scount = 0; }

#pragma unroll
    for (int pass = 0; pass < 2; pass++) {
        const int shift = 8 - pass * 8;
        hist[tid] = 0;
        __syncthreads();
        const uint32_t pref  = s_prefix;
        const int      kneed = s_k;
        const uint32_t hmask = (pass == 0) ? 0u : 0xFF00u;
#pragma unroll
        for (int j = 0; j < 8; j++)
            if ((key[j] & hmask) == pref)
                atomicAdd(&hist[(key[j] >> shift) & 255], 1);
        __syncthreads();

        if (tid < 32) {
            const int base = tid * 8;
            int h[8], ssum = 0;
#pragma unroll
            for (int j = 0; j < 8; j++) { h[j] = hist[base + j]; ssum += h[j]; }
            int suf = ssum;
#pragma unroll
            for (int off = 1; off < 32; off <<= 1) {
                int t = __shfl_down_sync(0xffffffffu, suf, off);
                if (tid + off < 32) suf += t;
            }
            int sufn = __shfl_down_sync(0xffffffffu, suf, 1);
            if (tid == 31) sufn = 0;
            if (suf >= kneed && sufn < kneed) {
                int cum = sufn;
#pragma unroll
                for (int j = 7; j >= 0; j--) {
                    cum += h[j];
                    if (cum >= kneed) {
                        s_prefix = pref | ((uint32_t)(base + j) << shift);
                        s_k      = kneed - (cum - h[j]);
                        break;
                    }
                }
            }
        }
        __syncthreads();
    }

    const float thr_lo = ord2bf(s_prefix) - MARGIN;

#pragma unroll
    for (int j = 0; j < 8; j++) {
        if (vals[j] >= thr_lo) {
            int i = atomicAdd(&scount, 1);
            if (i < NCAND) scols[i] = tid * 8 + j;
        }
    }
    __syncthreads();
    const int count = (scount < NCAND) ? scount : NCAND;

    const float* kb = k + (size_t)(b * H_) * N_ * D_;
    for (int i = wid; i < count; i += 8) {
        const int m = scols[i];
        float sum = 0.0f;
#pragma unroll
        for (int t = 0; t < 16; t++) {
            const int c = lid + 32 * t;
            sum += qs[c] * kb[(((size_t)(c >> 6) * N_ + m) << 6) + (c & 63)];
        }
#pragma unroll
        for (int off = 16; off; off >>= 1)
            sum += __shfl_xor_sync(0xffffffffu, sum, off);
        if (lid == 0)
            cand_z[i] = sum * FSCALE + gumbel_of(u[(size_t)row * N_ + m]);
    }
    __syncthreads();

    if (wid == 0) {
        float va  = (lid < count) ? cand_z[lid] : -1e30f;
        float vb2 = (32 + lid < count) ? cand_z[32 + lid] : -1e30f;
        float vc  = (64 + lid < count) ? cand_z[64 + lid] : -1e30f;
        int ca = 0, cb = 0, cc = 0;
        for (int j = 0; j < count; j++) {
            const float w = cand_z[j];
            ca += (w >= va); cb += (w >= vb2); cc += (w >= vc);
        }
        float t1 = (ca >= KTOP && lid < count) ? va : -1e30f;
        float t2 = (cb >= KTOP && 32 + lid < count) ? vb2 : -1e30f;
        float t3 = (cc >= KTOP && 64 + lid < count) ? vc : -1e30f;
        float mx = fmaxf(fmaxf(t1, t2), t3);
#pragma unroll
        for (int off = 16; off; off >>= 1)
            mx = fmaxf(mx, __shfl_xor_sync(0xffffffffu, mx, off));
        if (lid == 0) s_thresh = mx;
    }
    __syncthreads();
    const float thr = s_thresh;

    float mk[8] = {0, 0, 0, 0, 0, 0, 0, 0};
    for (int i = 0; i < count; i++) {
        if (cand_z[i] >= thr) {
            const int rel = scols[i] - tid * 8;
            if (rel >= 0 && rel < 8) mk[rel] = 1.0f;
        }
    }
    float* o = out + (size_t)row * N_ + tid * 8;
    *(float4*)(o)     = make_float4(mk[0], mk[1], mk[2], mk[3]);
    *(float4*)(o + 4) = make_float4(mk[4], mk[5], mk[6], mk[7]);
}

// ---------------------------------------------------------------------------
extern "C" void kernel_launch(void* const* d_in, const int* in_sizes, int n_in,
                              void* d_out, int out_size)
{
    const float* q = (const float*)d_in[0];
    const float* k = (const float*)d_in[1];
    const float* u = (const float*)d_in[2];
    float* out = (float*)d_out;

    cudaFuncSetAttribute(gemm_approx_kernel,
                         cudaFuncAttributeMaxDynamicSharedMemorySize, SMEM_TOTAL);

    dim3 cgrid(8192, 2);
    convert_kernel<<<cgrid, 256>>>(q, k, u);
    dim3 ggrid(N_ / 128, N_ / 128, B_);
    gemm_approx_kernel<<<ggrid, 512, SMEM_TOTAL>>>();
    topk_refine_kernel<<<B_ * N_, 256>>>(q, k, u, out);
}

// round 17
// speedup vs baseline: 1.1103x; 1.1103x over previous
#include <cuda_runtime.h>
#include <cuda_bf16.h>
#include <cstdint>

#define B_ 4
#define H_ 8
#define N_ 2048
#define D_ 64
#define KTOP 16
#define FSCALE (1.0f/64.0f)
#define MARGIN 0.08f
#define NCAND 96

#define NIT 8               // 512 / BK, BK=64 (one head per iter)
#define STAGE_BYTES 24576   // A tile 16KB + B tile 8KB
#define B_OFF 16384
#define SMEM_TOTAL (2 * STAGE_BYTES)   // 48KB -> 4 CTAs/SM

// ---- global scratch (allocation-free rule: __device__ globals) ----
__device__ unsigned short g_zb[(size_t)B_ * N_ * N_];   // z_approx bf16 bits
__device__ __nv_bfloat16 g_qs[(size_t)B_ * H_ * N_ * D_];
__device__ __nv_bfloat16 g_ks[(size_t)B_ * H_ * N_ * D_];

// ---------------------------------------------------------------------------
// helpers
// ---------------------------------------------------------------------------
__device__ __forceinline__ uint32_t smem_to_u32(const void* p) {
    uint32_t a;
    asm("{ .reg .u64 t; cvta.to.shared.u64 t, %1; cvt.u32.u64 %0, t; }" : "=r"(a) : "l"(p));
    return a;
}
__device__ __forceinline__ uint32_t tile_off(int row, int chunk) {
    return (uint32_t)(row * 128 + ((chunk ^ (row & 7)) << 4));
}
__device__ __forceinline__ void cp16(uint32_t dst, const void* src) {
    asm volatile("cp.async.cg.shared.global [%0], [%1], 16;" :: "r"(dst), "l"(src) : "memory");
}
__device__ __forceinline__ void cp_commit() {
    asm volatile("cp.async.commit_group;" ::: "memory");
}
template<int Ng> __device__ __forceinline__ void cp_wait() {
    asm volatile("cp.async.wait_group %0;" :: "n"(Ng) : "memory");
}
__device__ __forceinline__ void ldsm4(uint32_t* r, uint32_t addr) {
    asm volatile("ldmatrix.sync.aligned.m8n8.x4.shared.b16 {%0,%1,%2,%3}, [%4];"
                 : "=r"(r[0]), "=r"(r[1]), "=r"(r[2]), "=r"(r[3]) : "r"(addr));
}
__device__ __forceinline__ void mma_bf16(float* c, const uint32_t* a,
                                         uint32_t b0, uint32_t b1) {
    asm volatile(
        "mma.sync.aligned.m16n8k16.row.col.f32.bf16.bf16.f32 "
        "{%0,%1,%2,%3}, {%4,%5,%6,%7}, {%8,%9}, {%0,%1,%2,%3};"
        : "+f"(c[0]), "+f"(c[1]), "+f"(c[2]), "+f"(c[3])
        : "r"(a[0]), "r"(a[1]), "r"(a[2]), "r"(a[3]), "r"(b0), "r"(b1));
}
// accurate gumbel (exact refine path only)
__device__ __forceinline__ float gumbel_of(float u) {
    return -logf(-logf(u + 1e-9f) + 1e-9f);
}
// fast polynomial ln: range-reduce m in [2/3, 4/3), degree-7 Taylor.
__device__ __forceinline__ float fast_ln(float x) {
    const int i = __float_as_int(x);
    const int e = (i - 0x3f2aaaab) >> 23;
    const float m = __int_as_float(i - (e << 23));
    const float t = m - 1.0f;
    float p = -0.142857143f;
    p = fmaf(p, t, 0.166666667f);
    p = fmaf(p, t, -0.2f);
    p = fmaf(p, t, 0.25f);
    p = fmaf(p, t, -0.333333333f);
    p = fmaf(p, t, 0.5f);
    p = fmaf(p, t, -1.0f);
    return fmaf((float)e, 0.693147181f, -t * p);
}
__device__ __forceinline__ float gumbel_fast(float u) {
    const float v = -fast_ln(u + 1e-9f);
    return -fast_ln(v + 1e-9f);
}
__device__ __forceinline__ uint32_t pack_bf2(float a, float b) {
    return (uint32_t)__bfloat16_as_ushort(__float2bfloat16_rn(a))
         | ((uint32_t)__bfloat16_as_ushort(__float2bfloat16_rn(b)) << 16);
}
__device__ __forceinline__ float bf_bits2f(unsigned short v) {
    return __bfloat162float(__ushort_as_bfloat16(v));
}

// ---------------------------------------------------------------------------
// Kernel 0: fp32 -> bf16 cast (layout preserved). grid (2048, 2).
// ---------------------------------------------------------------------------
__global__ __launch_bounds__(256) void convert_kernel(
    const float* __restrict__ q, const float* __restrict__ k)
{
    const size_t e = ((size_t)blockIdx.x * 256 + threadIdx.x) * 8;
    const float* src = blockIdx.y ? k : q;
    __nv_bfloat16* dst = blockIdx.y ? g_ks : g_qs;
    float4 a = *(const float4*)(src + e);
    float4 b = *(const float4*)(src + e + 4);
    uint4 o;
    o.x = pack_bf2(a.x, a.y);
    o.y = pack_bf2(a.z, a.w);
    o.z = pack_bf2(b.x, b.y);
    o.w = pack_bf2(b.z, b.w);
    *(uint4*)(dst + e) = o;
}

// ---------------------------------------------------------------------------
// Kernel 1: 1-term bf16 mma.sync GEMM + fast gumbel -> z_approx (bf16).
// CTA tile 128(n) x 64(m), BK=64, 256 threads = 8 warps (4m x 2n),
// warp tile 32x32. 4 CTAs/SM -> 32 warps/SM. cp.async 2-stage pipeline.
// ---------------------------------------------------------------------------
__global__ __launch_bounds__(256, 4) void gemm_approx_kernel(
    const float* __restrict__ u)
{
    extern __shared__ char smem[];
    const uint32_t sbase = smem_to_u32(smem);

    const int tid = threadIdx.x;
    const int lid = tid & 31;
    const int wid = tid >> 5;          // 0..7
    const int wm  = wid >> 1;          // 0..3 : 32-row block (of 128)
    const int wn  = wid & 1;           // 0..1 : 32-col block (of 64)

    const int b  = blockIdx.z;
    const int m0 = blockIdx.x * 64;    // z cols (K rows), 32 tiles
    const int n0 = blockIdx.y * 128;   // z rows (Q rows), 16 tiles

    // A loader: each thread 4 chunks of one row-half (1024 cp16 total)
    const int larow  = tid >> 1;
    const int lahalf = tid & 1;
    const __nv_bfloat16* lsrcA =
        g_qs + ((size_t)(b * H_) * N_ + (n0 + larow)) * D_ + lahalf * 32;
    // B loader: each thread 2 chunks (512 cp16 total)
    const int lbrow = tid >> 2;
    const int lbch  = (tid & 3) * 2;
    const __nv_bfloat16* lsrcB =
        g_ks + ((size_t)(b * H_) * N_ + (m0 + lbrow)) * D_ + lbch * 8;
    const size_t plane = (size_t)N_ * D_;

    float acc[2][4][4];
#pragma unroll
    for (int i = 0; i < 2; i++)
#pragma unroll
        for (int j = 0; j < 4; j++)
#pragma unroll
            for (int t = 0; t < 4; t++) acc[i][j][t] = 0.0f;

    // ldmatrix lane addressing
    const int ar = lid & 15;
    const int ac = lid >> 4;
    const int br = (lid & 7) + ((lid >> 4) << 3);
    const int bc = (lid >> 3) & 1;

    {   // prologue: stage 0
#pragma unroll
        for (int c = 0; c < 4; c++)
            cp16(sbase + tile_off(larow, lahalf * 4 + c), (const char*)lsrcA + c * 16);
#pragma unroll
        for (int c = 0; c < 2; c++)
            cp16(sbase + B_OFF + tile_off(lbrow, lbch + c), (const char*)lsrcB + c * 16);
        cp_commit();
    }

#pragma unroll 1
    for (int it = 0; it < NIT; it++) {
        const int stg = it & 1;
        cp_wait<0>();
        __syncthreads();

        if (it + 1 < NIT) {
            const __nv_bfloat16* srcA = lsrcA + (size_t)(it + 1) * plane;
            const __nv_bfloat16* srcB = lsrcB + (size_t)(it + 1) * plane;
            const uint32_t dbase = sbase + (uint32_t)((1 - stg) * STAGE_BYTES);
#pragma unroll
            for (int c = 0; c < 4; c++)
                cp16(dbase + tile_off(larow, lahalf * 4 + c), (const char*)srcA + c * 16);
#pragma unroll
            for (int c = 0; c < 2; c++)
                cp16(dbase + B_OFF + tile_off(lbrow, lbch + c), (const char*)srcB + c * 16);
            cp_commit();
        }

        const uint32_t abase   = sbase + (uint32_t)(stg * STAGE_BYTES);
        const uint32_t bbase_s = abase + B_OFF;

#pragma unroll
        for (int s = 0; s < 4; s++) {          // 4 k16 steps per BK=64
            uint32_t ah[2][4], bb[2][4];
            ldsm4(ah[0], abase + tile_off(wm * 32 + ar, s * 2 + ac));
            ldsm4(ah[1], abase + tile_off(wm * 32 + 16 + ar, s * 2 + ac));
            ldsm4(bb[0], bbase_s + tile_off(wn * 32 + br, s * 2 + bc));
            ldsm4(bb[1], bbase_s + tile_off(wn * 32 + 16 + br, s * 2 + bc));
#pragma unroll
            for (int g = 0; g < 2; g++)
#pragma unroll
                for (int mf = 0; mf < 2; mf++) {
                    mma_bf16(acc[mf][g * 2 + 0], ah[mf], bb[g][0], bb[g][1]);
                    mma_bf16(acc[mf][g * 2 + 1], ah[mf], bb[g][2], bb[g][3]);
                }
        }
    }

    // Epilogue: z = acc*FSCALE + gumbel_fast(u) -> bf16 in g_zb
    const int r4 = lid >> 2;
    const int c2 = (lid & 3) * 2;
#pragma unroll
    for (int mf = 0; mf < 2; mf++) {
#pragma unroll
        for (int rr = 0; rr < 2; rr++) {
            const int row = n0 + wm * 32 + mf * 16 + r4 + rr * 8;
            const size_t rbase = ((size_t)b * N_ + row) * N_ + m0 + wn * 32;
            const float* urow = u + rbase;
            unsigned short* zrow = g_zb + rbase;
#pragma unroll
            for (int j = 0; j < 4; j++) {
                const int co = (j >> 1) * 16 + (j & 1) * 8 + c2;
                float2 uv = *(const float2*)(urow + co);
                const float zx = acc[mf][j][rr * 2 + 0] * FSCALE + gumbel_fast(uv.x);
                const float zy = acc[mf][j][rr * 2 + 1] * FSCALE + gumbel_fast(uv.y);
                *(uint32_t*)(zrow + co) = pack_bf2(zx, zy);
            }
        }
    }
}

// ---------------------------------------------------------------------------
// Kernel 2: 16-bit radix select on z_approx (2 passes) -> candidates within
// MARGIN -> exact fp32 recompute (original q,k) -> exact 16th-largest -> mask.
// (R14 version: one row per 256-thread block)
// ---------------------------------------------------------------------------
__device__ __forceinline__ uint32_t bf2ord(unsigned short v) {
    return (v & 0x8000u) ? ((~(uint32_t)v) & 0xFFFFu) : ((uint32_t)v | 0x8000u);
}
__device__ __forceinline__ float ord2bf(uint32_t o) {
    unsigned short v = (o & 0x8000u) ? (unsigned short)(o & 0x7FFFu)
                                     : (unsigned short)((~o) & 0xFFFFu);
    return bf_bits2f(v);
}

__global__ __launch_bounds__(256) void topk_refine_kernel(
    const float* __restrict__ q, const float* __restrict__ k,
    const float* __restrict__ u, float* __restrict__ out)
{
    const int row = blockIdx.x;            // b*2048 + n
    const int b = row >> 11;
    const int n = row & 2047;
    const int tid = threadIdx.x;
    const int lid = tid & 31, wid = tid >> 5;

    __shared__ int      hist[256];
    __shared__ uint32_t s_prefix;
    __shared__ int      s_k;
    __shared__ float    qs[512];
    __shared__ int      scols[NCAND];
    __shared__ float    cand_z[NCAND];
    __shared__ int      scount;
    __shared__ float    s_thresh;

    const unsigned short* zr = g_zb + (size_t)row * N_;
    uint4 rz = ((const uint4*)zr)[tid];
    unsigned short vb[8] = {
        (unsigned short)(rz.x & 0xFFFF), (unsigned short)(rz.x >> 16),
        (unsigned short)(rz.y & 0xFFFF), (unsigned short)(rz.y >> 16),
        (unsigned short)(rz.z & 0xFFFF), (unsigned short)(rz.z >> 16),
        (unsigned short)(rz.w & 0xFFFF), (unsigned short)(rz.w >> 16)};
    uint32_t key[8];
    float vals[8];
#pragma unroll
    for (int j = 0; j < 8; j++) { key[j] = bf2ord(vb[j]); vals[j] = bf_bits2f(vb[j]); }

    {
        int c = tid;
        qs[c] = q[(((size_t)(b * H_ + (c >> 6)) * N_ + n) << 6) + (c & 63)];
        c = tid + 256;
        qs[c] = q[(((size_t)(b * H_ + (c >> 6)) * N_ + n) << 6) + (c & 63)];
    }
    if (tid == 0) { s_prefix = 0u; s_k = KTOP; scount = 0; }

#pragma unroll
    for (int pass = 0; pass < 2; pass++) {
        const int shift = 8 - pass * 8;
        hist[tid] = 0;
        __syncthreads();
        const uint32_t pref  = s_prefix;
        const int      kneed = s_k;
        const uint32_t hmask = (pass == 0) ? 0u : 0xFF00u;
#pragma unroll
        for (int j = 0; j < 8; j++)
            if ((key[j] & hmask) == pref)
                atomicAdd(&hist[(key[j] >> shift) & 255], 1);
        __syncthreads();

        if (tid < 32) {
            const int base = tid * 8;
            int h[8], ssum = 0;
#pragma unroll
            for (int j = 0; j < 8; j++) { h[j] = hist[base + j]; ssum += h[j]; }
            int suf = ssum;
#pragma unroll
            for (int off = 1; off < 32; off <<= 1) {
                int t = __shfl_down_sync(0xffffffffu, suf, off);
                if (tid + off < 32) suf += t;
            }
            int sufn = __shfl_down_sync(0xffffffffu, suf, 1);
            if (tid == 31) sufn = 0;
            if (suf >= kneed && sufn < kneed) {
                int cum = sufn;
#pragma unroll
                for (int j = 7; j >= 0; j--) {
                    cum += h[j];
                    if (cum >= kneed) {
                        s_prefix = pref | ((uint32_t)(base + j) << shift);
                        s_k      = kneed - (cum - h[j]);
                        break;
                    }
                }
            }
        }
        __syncthreads();
    }

    const float thr_lo = ord2bf(s_prefix) - MARGIN;

#pragma unroll
    for (int j = 0; j < 8; j++) {
        if (vals[j] >= thr_lo) {
            int i = atomicAdd(&scount, 1);
            if (i < NCAND) scols[i] = tid * 8 + j;
        }
    }
    __syncthreads();
    const int count = (scount < NCAND) ? scount : NCAND;

    const float* kb = k + (size_t)(b * H_) * N_ * D_;
    for (int i = wid; i < count; i += 8) {
        const int m = scols[i];
        float sum = 0.0f;
#pragma unroll
        for (int t = 0; t < 16; t++) {
            const int c = lid + 32 * t;
            sum += qs[c] * kb[(((size_t)(c >> 6) * N_ + m) << 6) + (c & 63)];
        }
#pragma unroll
        for (int off = 16; off; off >>= 1)
            sum += __shfl_xor_sync(0xffffffffu, sum, off);
        if (lid == 0)
            cand_z[i] = sum * FSCALE + gumbel_of(u[(size_t)row * N_ + m]);
    }
    __syncthreads();

    if (wid == 0) {
        float va  = (lid < count) ? cand_z[lid] : -1e30f;
        float vb2 = (32 + lid < count) ? cand_z[32 + lid] : -1e30f;
        float vc  = (64 + lid < count) ? cand_z[64 + lid] : -1e30f;
        int ca = 0, cb = 0, cc = 0;
        for (int j = 0; j < count; j++) {
            const float w = cand_z[j];
            ca += (w >= va); cb += (w >= vb2); cc += (w >= vc);
        }
        float t1 = (ca >= KTOP && lid < count) ? va : -1e30f;
        float t2 = (cb >= KTOP && 32 + lid < count) ? vb2 : -1e30f;
        float t3 = (cc >= KTOP && 64 + lid < count) ? vc : -1e30f;
        float mx = fmaxf(fmaxf(t1, t2), t3);
#pragma unroll
        for (int off = 16; off; off >>= 1)
            mx = fmaxf(mx, __shfl_xor_sync(0xffffffffu, mx, off));
        if (lid == 0) s_thresh = mx;
    }
    __syncthreads();
    const float thr = s_thresh;

    float mk[8] = {0, 0, 0, 0, 0, 0, 0, 0};
    for (int i = 0; i < count; i++) {
        if (cand_z[i] >= thr) {
            const int rel = scols[i] - tid * 8;
            if (rel >= 0 && rel < 8) mk[rel] = 1.0f;
        }
    }
    float* o = out + (size_t)row * N_ + tid * 8;
    *(float4*)(o)     = make_float4(mk[0], mk[1], mk[2], mk[3]);
    *(float4*)(o + 4) = make_float4(mk[4], mk[5], mk[6], mk[7]);
}

// ---------------------------------------------------------------------------
// Dummy no-op kernel: rotates which launch ncu's -s 5 -c 1 captures,
// so next round's profile lands on gemm or refine instead of convert.
// ---------------------------------------------------------------------------
__global__ void dummy_kernel() {}

// ---------------------------------------------------------------------------
extern "C" void kernel_launch(void* const* d_in, const int* in_sizes, int n_in,
                              void* d_out, int out_size)
{
    const float* q = (const float*)d_in[0];
    const float* k = (const float*)d_in[1];
    const float* u = (const float*)d_in[2];
    float* out = (float*)d_out;

    cudaFuncSetAttribute(gemm_approx_kernel,
                         cudaFuncAttributeMaxDynamicSharedMemorySize, SMEM_TOTAL);

    dim3 cgrid(2048, 2);
    convert_kernel<<<cgrid, 256>>>(q, k);
    dim3 ggrid(N_ / 64, N_ / 128, B_);      // 32 x 16 x 4 = 2048 CTAs
    gemm_approx_kernel<<<ggrid, 256, SMEM_TOTAL>>>(u);
    topk_refine_kernel<<<B_ * N_, 256>>>(q, k, u, out);
    dummy_kernel<<<1, 32>>>();
}